// round 9
// baseline (speedup 1.0000x reference)
#include <cuda_runtime.h>

#define Hh 64
#define FF 36
#define Ww 8
#define Ss 200
#define KSTRIDE 68       // frag loads: bank = (4*g + t) mod 32 -> all 32 distinct
#define NTHREADS 256

// smem layout in floats
#define OFF_K    0                        // 208*68 = 14144 (rows 200..207 zeroed)
#define OFF_MHI  14144                    // 40*68 = 2720 (rows 36..39 zero)
#define OFF_MLO  (OFF_MHI + 2720)         // 2720
#define OFF_SC   (OFF_MLO + 2720)         // 200
#define OFF_RED  (OFF_SC + 200)           // 256
#define OFF_D    (OFF_RED + 256)          // 40 (36..39 zero)
#define OFF_W2   (OFF_D + 40)             // 40 (36..39 zero)
#define OFF_Q    (OFF_W2 + 40)            // 64
#define OFF_MISC (OFF_Q + Hh)             // 4: smax, ssum, b2, prelu_a
#define SMEM_FLOATS (OFF_MISC + 4)        // 20188 floats = 80.8 KB -> 2 CTAs/SM

// 0 = mask is int32 (one word per element), 1 = mask is packed bytes (uint8)
__device__ int g_mask_is_bytes;

__global__ void detect_mask_layout(const unsigned int* __restrict__ m, int nwords) {
    __shared__ int found;
    if (threadIdx.x == 0) found = 0;
    __syncthreads();
    int f = 0;
    for (int i = threadIdx.x; i < nwords; i += blockDim.x)
        f |= (m[i] > 1u);
    if (f) atomicOr(&found, 1);
    __syncthreads();
    if (threadIdx.x == 0) g_mask_is_bytes = found;
}

__device__ __forceinline__ unsigned f2tf32(float x) {
    unsigned r;
    asm("cvt.rna.tf32.f32 %0, %1;" : "=r"(r) : "f"(x));
    return r;
}
__device__ __forceinline__ float lds_f32(unsigned a) {
    float v; asm volatile("ld.shared.f32 %0, [%1];" : "=f"(v) : "r"(a)); return v;
}
__device__ __forceinline__ unsigned lds_u32(unsigned a) {
    unsigned v; asm volatile("ld.shared.b32 %0, [%1];" : "=r"(v) : "r"(a)); return v;
}
__device__ __forceinline__ void mma_tf32(float* c, const unsigned* a,
                                         unsigned b0, unsigned b1) {
    asm volatile(
        "mma.sync.aligned.m16n8k8.row.col.f32.tf32.tf32.f32 "
        "{%0,%1,%2,%3}, {%4,%5,%6,%7}, {%8,%9}, {%0,%1,%2,%3};"
        : "+f"(c[0]), "+f"(c[1]), "+f"(c[2]), "+f"(c[3])
        : "r"(a[0]), "r"(a[1]), "r"(a[2]), "r"(a[3]), "r"(b0), "r"(b1));
}

extern "C" __global__ void __launch_bounds__(NTHREADS, 2)
twb_kernel(const float* __restrict__ query,
           const float* __restrict__ key,
           const float* __restrict__ W1,
           const float* __restrict__ b1,
           const float* __restrict__ prelu_a,
           const float* __restrict__ W2,
           const float* __restrict__ b2,
           const void* __restrict__ mask,
           float* __restrict__ out)
{
    extern __shared__ float sm[];
    const int bw  = blockIdx.x;     // b*W + w
    const int b   = bw >> 3;        // W = 8
    const int tid = threadIdx.x;

    // ---- small loads + padding init ----
    if (tid < Hh) sm[OFF_Q + tid]  = query[b * Hh + tid];
    if (tid < 40) sm[OFF_W2 + tid] = (tid < FF) ? W2[tid] : 0.f;
    if (tid == 0) { sm[OFF_MISC + 2] = b2[0]; sm[OFF_MISC + 3] = prelu_a[0]; }
    // zero K pad rows 200..207
    for (int i = tid; i < 8 * KSTRIDE; i += NTHREADS)
        sm[OFF_K + Ss * KSTRIDE + i] = 0.f;
    __syncthreads();

    // ---- stage K tile (200x64) into smem, stride 68 ----
    {
        const float4* gk = (const float4*)(key + (size_t)bw * Ss * Hh);
        for (int i = tid; i < Ss * Hh / 4; i += NTHREADS) {
            int s = i >> 4, c = i & 15;
            float4 v = gk[i];
            *(float4*)&sm[OFF_K + s * KSTRIDE + c * 4] = v;
        }
    }

    // ---- build M_b split into tf32 hi/lo (rows 36..39 zero), and d_b ----
    {
        const float* q = &sm[OFF_Q];
        for (int idx = tid; idx < 40 * Hh; idx += NTHREADS) {
            int o = idx >> 6, h = idx & 63;
            float m = 0.f;
            if (o < FF) {
                const float* w = W1 + o * 4 * Hh;
                m = w[Hh + h] - w[2 * Hh + h] + w[3 * Hh + h] * q[h];
            }
            unsigned hi = f2tf32(m);
            float lo = m - __uint_as_float(hi);
            sm[OFF_MHI + o * KSTRIDE + h] = __uint_as_float(hi);
            sm[OFF_MLO + o * KSTRIDE + h] = __uint_as_float(f2tf32(lo));
        }
        if (tid < 40) {
            float acc = 0.f;
            if (tid < FF) {
                const float* w = W1 + tid * 4 * Hh;
                acc = b1[tid];
                #pragma unroll 8
                for (int h = 0; h < Hh; h++)
                    acc += (w[h] + w[2 * Hh + h]) * q[h];
            }
            sm[OFF_D + tid] = acc;
        }
    }
    __syncthreads();

    // ==== tensor-core score GEMM: H[s,o] = K[s,:].M[o,:] via 3x tf32 mma ====
    // m = s (13 m16 tiles), n = o (5 n8 tiles), k = h (8 k8 steps).
    {
        const int wid  = tid >> 5;
        const int lane = tid & 31;
        const int g    = lane >> 2;   // group row
        const int t    = lane & 3;    // thread-in-group
        const unsigned ksm = (unsigned)__cvta_generic_to_shared(&sm[OFF_K]);
        const unsigned mhi = (unsigned)__cvta_generic_to_shared(&sm[OFF_MHI]);
        const unsigned mlo = (unsigned)__cvta_generic_to_shared(&sm[OFF_MLO]);
        const float ap  = sm[OFF_MISC + 3];
        const float bb2 = sm[OFF_MISC + 2];

        for (int mt = wid; mt < 13; mt += 8) {
            const int mb = mt * 16;

            // A fragments (K rows), split into tf32 hi/lo in registers
            unsigned ahi[8][4], alo[8][4];
            #pragma unroll
            for (int kt = 0; kt < 8; kt++) {
                #pragma unroll
                for (int j = 0; j < 4; j++) {
                    int row = mb + g + (j & 1) * 8;
                    int col = kt * 8 + t + (j >> 1) * 4;
                    float v = lds_f32(ksm + (unsigned)(row * KSTRIDE + col) * 4u);
                    unsigned hb = f2tf32(v);
                    ahi[kt][j] = hb;
                    alo[kt][j] = f2tf32(v - __uint_as_float(hb));
                }
            }

            float acc[5][4];
            #pragma unroll
            for (int nt = 0; nt < 5; nt++) {
                #pragma unroll
                for (int j = 0; j < 4; j++) acc[nt][j] = 0.f;
                #pragma unroll
                for (int kt = 0; kt < 8; kt++) {
                    unsigned boff = (unsigned)((nt * 8 + g) * KSTRIDE + kt * 8 + t) * 4u;
                    unsigned bh0 = lds_u32(mhi + boff);
                    unsigned bh1 = lds_u32(mhi + boff + 16u);
                    unsigned bl0 = lds_u32(mlo + boff);
                    unsigned bl1 = lds_u32(mlo + boff + 16u);
                    mma_tf32(acc[nt], ahi[kt], bh0, bh1);
                    mma_tf32(acc[nt], ahi[kt], bl0, bl1);
                    mma_tf32(acc[nt], alo[kt], bh0, bh1);
                }
            }

            // epilogue: h -> PReLU -> W2 dot, reduce over 4-lane group
            float p0 = 0.f, p1 = 0.f;           // rows mb+g, mb+g+8
            #pragma unroll
            for (int nt = 0; nt < 5; nt++) {
                #pragma unroll
                for (int j = 0; j < 2; j++) {
                    int o = nt * 8 + 2 * t + j;
                    float dv = sm[OFF_D + o], wv = sm[OFF_W2 + o];
                    float h0 = acc[nt][j] + dv;
                    h0 = h0 >= 0.f ? h0 : ap * h0;
                    p0 += wv * h0;
                    float h1 = acc[nt][2 + j] + dv;
                    h1 = h1 >= 0.f ? h1 : ap * h1;
                    p1 += wv * h1;
                }
            }
            p0 += __shfl_xor_sync(0xffffffffu, p0, 1);
            p0 += __shfl_xor_sync(0xffffffffu, p0, 2);
            p1 += __shfl_xor_sync(0xffffffffu, p1, 1);
            p1 += __shfl_xor_sync(0xffffffffu, p1, 2);

            if (t == 0) {
                int s0 = mb + g, s1 = mb + g + 8;
                if (s0 < Ss) {
                    int mk = g_mask_is_bytes
                           ? ((const unsigned char*)mask)[(size_t)bw * Ss + s0]
                           : ((const int*)mask)[(size_t)bw * Ss + s0];
                    sm[OFF_SC + s0] = mk ? -10000.0f : (p0 + bb2);
                }
                if (s1 < Ss) {
                    int mk = g_mask_is_bytes
                           ? ((const unsigned char*)mask)[(size_t)bw * Ss + s1]
                           : ((const int*)mask)[(size_t)bw * Ss + s1];
                    sm[OFF_SC + s1] = mk ? -10000.0f : (p1 + bb2);
                }
            }
        }
    }
    __syncthreads();

    // ---- softmax over S ----
    if (tid < 32) {
        float m = -3.4e38f;
        for (int i = tid; i < Ss; i += 32) m = fmaxf(m, sm[OFF_SC + i]);
        #pragma unroll
        for (int off = 16; off; off >>= 1)
            m = fmaxf(m, __shfl_xor_sync(0xffffffffu, m, off));
        if (tid == 0) sm[OFF_MISC + 0] = m;
    }
    __syncthreads();
    const float smax = sm[OFF_MISC + 0];
    if (tid < Ss) sm[OFF_SC + tid] = __expf(sm[OFF_SC + tid] - smax);
    __syncthreads();
    if (tid < 32) {
        float sum = 0.f;
        for (int i = tid; i < Ss; i += 32) sum += sm[OFF_SC + i];
        #pragma unroll
        for (int off = 16; off; off >>= 1)
            sum += __shfl_xor_sync(0xffffffffu, sum, off);
        if (tid == 0) sm[OFF_MISC + 1] = sum;
    }
    __syncthreads();
    const float inv = 1.0f / sm[OFF_MISC + 1];

    // ---- weighted sum: out[h] = inv * sum_s e[s]*k[s][h] ----
    {
        int h = tid & 63, g = tid >> 6;   // 4 s-groups x 64 h
        float acc = 0.f;
        for (int s = g; s < Ss; s += 4)
            acc += sm[OFF_SC + s] * sm[OFF_K + s * KSTRIDE + h];
        sm[OFF_RED + g * 64 + h] = acc;
    }
    __syncthreads();
    if (tid < Hh) {
        float v = sm[OFF_RED + tid] + sm[OFF_RED + 64 + tid]
                + sm[OFF_RED + 128 + tid] + sm[OFF_RED + 192 + tid];
        out[(size_t)bw * Hh + tid] = v * inv;
    }
}

extern "C" void kernel_launch(void* const* d_in, const int* in_sizes, int n_in,
                              void* d_out, int out_size) {
    const float* query          = (const float*)d_in[0];
    const float* key            = (const float*)d_in[1];
    const float* W1             = (const float*)d_in[2];
    const float* b1             = (const float*)d_in[3];
    const float* prelu_a        = (const float*)d_in[4];
    const float* W2             = (const float*)d_in[5];
    const float* b2             = (const float*)d_in[6];
    const void*  mask           = (const void*)d_in[7];
    float* out = (float*)d_out;

    const int B = in_sizes[0] / Hh;      // 512
    const int grid = B * Ww;             // 4096 CTAs, one per (b,w)
    const int smem_bytes = SMEM_FLOATS * sizeof(float);   // ~80.8 KB

    detect_mask_layout<<<1, 1024>>>((const unsigned int*)mask, 65536);

    cudaFuncSetAttribute(twb_kernel,
                         cudaFuncAttributeMaxDynamicSharedMemorySize, smem_bytes);
    twb_kernel<<<grid, NTHREADS, smem_bytes>>>(
        query, key, W1, b1, prelu_a, W2, b2, mask, out);
}

// round 10
// speedup vs baseline: 1.3611x; 1.3611x over previous
#include <cuda_runtime.h>

#define Hh 64
#define FF 36
#define Ww 8
#define Ss 200
#define KSTRIDE 68       // frag loads: bank = (4*g + t) mod 32 -> all 32 distinct
#define NTHREADS 512

// smem layout in floats
#define OFF_K    0                        // 208*68 = 14144 (rows 200..207 zeroed)
#define OFF_MHI  14144                    // 40*68 = 2720 (rows 36..39 zero)
#define OFF_MLO  (OFF_MHI + 2720)         // 2720
#define OFF_SC   (OFF_MLO + 2720)         // 200
#define OFF_RED  (OFF_SC + 200)           // 512 (8 s-groups x 64 h)
#define OFF_D    (OFF_RED + 512)          // 40 (36..39 zero)
#define OFF_W2   (OFF_D + 40)             // 40 (36..39 zero)
#define OFF_Q    (OFF_W2 + 40)            // 64
#define OFF_MISC (OFF_Q + Hh)             // 4: smax, ssum, b2, prelu_a
#define SMEM_FLOATS (OFF_MISC + 4)        // 20444 floats = 81.8 KB -> 2 CTAs/SM

// 0 = mask is int32 (one word per element), 1 = mask is packed bytes (uint8)
__device__ int g_mask_is_bytes;

// Tiny scan: 1024 words is overwhelming evidence either way, ~2us.
__global__ void detect_mask_layout(const unsigned int* __restrict__ m, int nwords) {
    __shared__ int found;
    if (threadIdx.x == 0) found = 0;
    __syncthreads();
    int f = 0;
    for (int i = threadIdx.x; i < nwords; i += blockDim.x)
        f |= (m[i] > 1u);
    if (f) atomicOr(&found, 1);
    __syncthreads();
    if (threadIdx.x == 0) g_mask_is_bytes = found;
}

__device__ __forceinline__ unsigned f2tf32(float x) {
    unsigned r;
    asm("cvt.rna.tf32.f32 %0, %1;" : "=r"(r) : "f"(x));
    return r;
}
__device__ __forceinline__ float lds_f32(unsigned a) {
    float v; asm volatile("ld.shared.f32 %0, [%1];" : "=f"(v) : "r"(a)); return v;
}
__device__ __forceinline__ unsigned lds_u32(unsigned a) {
    unsigned v; asm volatile("ld.shared.b32 %0, [%1];" : "=r"(v) : "r"(a)); return v;
}
__device__ __forceinline__ void mma_tf32(float* c, const unsigned* a,
                                         unsigned b0, unsigned b1) {
    asm volatile(
        "mma.sync.aligned.m16n8k8.row.col.f32.tf32.tf32.f32 "
        "{%0,%1,%2,%3}, {%4,%5,%6,%7}, {%8,%9}, {%0,%1,%2,%3};"
        : "+f"(c[0]), "+f"(c[1]), "+f"(c[2]), "+f"(c[3])
        : "r"(a[0]), "r"(a[1]), "r"(a[2]), "r"(a[3]), "r"(b0), "r"(b1));
}

extern "C" __global__ void __launch_bounds__(NTHREADS, 2)
twb_kernel(const float* __restrict__ query,
           const float* __restrict__ key,
           const float* __restrict__ W1,
           const float* __restrict__ b1,
           const float* __restrict__ prelu_a,
           const float* __restrict__ W2,
           const float* __restrict__ b2,
           const void* __restrict__ mask,
           float* __restrict__ out)
{
    extern __shared__ float sm[];
    const int bw  = blockIdx.x;     // b*W + w
    const int b   = bw >> 3;        // W = 8
    const int tid = threadIdx.x;

    // ---- small loads + padding init ----
    if (tid < Hh) sm[OFF_Q + tid]  = query[b * Hh + tid];
    if (tid < 40) sm[OFF_W2 + tid] = (tid < FF) ? W2[tid] : 0.f;
    if (tid == 0) { sm[OFF_MISC + 2] = b2[0]; sm[OFF_MISC + 3] = prelu_a[0]; }
    // zero K pad rows 200..207
    for (int i = tid; i < 8 * KSTRIDE; i += NTHREADS)
        sm[OFF_K + Ss * KSTRIDE + i] = 0.f;
    __syncthreads();

    // ---- stage K tile (200x64) into smem, stride 68 ----
    {
        const float4* gk = (const float4*)(key + (size_t)bw * Ss * Hh);
        for (int i = tid; i < Ss * Hh / 4; i += NTHREADS) {
            int s = i >> 4, c = i & 15;
            float4 v = gk[i];
            *(float4*)&sm[OFF_K + s * KSTRIDE + c * 4] = v;
        }
    }

    // ---- build M_b split into tf32 hi/lo (rows 36..39 zero), and d_b ----
    {
        const float* q = &sm[OFF_Q];
        for (int idx = tid; idx < 40 * Hh; idx += NTHREADS) {
            int o = idx >> 6, h = idx & 63;
            float m = 0.f;
            if (o < FF) {
                const float* w = W1 + o * 4 * Hh;
                m = w[Hh + h] - w[2 * Hh + h] + w[3 * Hh + h] * q[h];
            }
            unsigned hi = f2tf32(m);
            float lo = m - __uint_as_float(hi);
            sm[OFF_MHI + o * KSTRIDE + h] = __uint_as_float(hi);
            sm[OFF_MLO + o * KSTRIDE + h] = __uint_as_float(f2tf32(lo));
        }
        if (tid < 40) {
            float acc = 0.f;
            if (tid < FF) {
                const float* w = W1 + tid * 4 * Hh;
                acc = b1[tid];
                #pragma unroll 8
                for (int h = 0; h < Hh; h++)
                    acc += (w[h] + w[2 * Hh + h]) * q[h];
            }
            sm[OFF_D + tid] = acc;
        }
    }
    __syncthreads();

    // ==== tensor-core score GEMM: H[s,o] = K[s,:].M[o,:] via 3x tf32 mma ====
    // m = s (13 m16 tiles, one per warp), n = o (5 n8 tiles), k = h (8 k8 steps).
    // kt-outer loop keeps A-fragments transient: ~55 live regs -> fits 64-reg cap.
    {
        const int wid  = tid >> 5;
        const int lane = tid & 31;
        const int g    = lane >> 2;   // group row
        const int t    = lane & 3;    // thread-in-group

        if (wid < 13) {
            const int mb = wid * 16;
            const unsigned ksm = (unsigned)__cvta_generic_to_shared(&sm[OFF_K]);
            const unsigned mhi = (unsigned)__cvta_generic_to_shared(&sm[OFF_MHI]);
            const unsigned mlo = (unsigned)__cvta_generic_to_shared(&sm[OFF_MLO]);

            float acc[5][4];
            #pragma unroll
            for (int nt = 0; nt < 5; nt++)
                #pragma unroll
                for (int j = 0; j < 4; j++) acc[nt][j] = 0.f;

            #pragma unroll
            for (int kt = 0; kt < 8; kt++) {
                // A fragment for this kt (K rows), split hi/lo
                unsigned ahi[4], alo[4];
                #pragma unroll
                for (int j = 0; j < 4; j++) {
                    int row = mb + g + (j & 1) * 8;
                    int col = kt * 8 + t + (j >> 1) * 4;
                    float v = lds_f32(ksm + (unsigned)(row * KSTRIDE + col) * 4u);
                    unsigned hb = f2tf32(v);
                    ahi[j] = hb;
                    alo[j] = f2tf32(v - __uint_as_float(hb));
                }
                #pragma unroll
                for (int nt = 0; nt < 5; nt++) {
                    unsigned boff =
                        (unsigned)((nt * 8 + g) * KSTRIDE + kt * 8 + t) * 4u;
                    unsigned bh0 = lds_u32(mhi + boff);
                    unsigned bh1 = lds_u32(mhi + boff + 16u);
                    unsigned bl0 = lds_u32(mlo + boff);
                    unsigned bl1 = lds_u32(mlo + boff + 16u);
                    mma_tf32(acc[nt], ahi, bh0, bh1);
                    mma_tf32(acc[nt], ahi, bl0, bl1);
                    mma_tf32(acc[nt], alo, bh0, bh1);
                }
            }

            // epilogue: h -> PReLU -> W2 dot, reduce over 4-lane group
            const float ap  = sm[OFF_MISC + 3];
            const float bb2 = sm[OFF_MISC + 2];
            float p0 = 0.f, p1 = 0.f;           // rows mb+g, mb+g+8
            #pragma unroll
            for (int nt = 0; nt < 5; nt++) {
                #pragma unroll
                for (int j = 0; j < 2; j++) {
                    int o = nt * 8 + 2 * t + j;
                    float dv = sm[OFF_D + o], wv = sm[OFF_W2 + o];
                    float h0 = acc[nt][j] + dv;
                    h0 = h0 >= 0.f ? h0 : ap * h0;
                    p0 += wv * h0;
                    float h1 = acc[nt][2 + j] + dv;
                    h1 = h1 >= 0.f ? h1 : ap * h1;
                    p1 += wv * h1;
                }
            }
            p0 += __shfl_xor_sync(0xffffffffu, p0, 1);
            p0 += __shfl_xor_sync(0xffffffffu, p0, 2);
            p1 += __shfl_xor_sync(0xffffffffu, p1, 1);
            p1 += __shfl_xor_sync(0xffffffffu, p1, 2);

            if (t == 0) {
                int s0 = mb + g, s1 = mb + g + 8;
                if (s0 < Ss) {
                    int mk = g_mask_is_bytes
                           ? ((const unsigned char*)mask)[(size_t)bw * Ss + s0]
                           : ((const int*)mask)[(size_t)bw * Ss + s0];
                    sm[OFF_SC + s0] = mk ? -10000.0f : (p0 + bb2);
                }
                if (s1 < Ss) {
                    int mk = g_mask_is_bytes
                           ? ((const unsigned char*)mask)[(size_t)bw * Ss + s1]
                           : ((const int*)mask)[(size_t)bw * Ss + s1];
                    sm[OFF_SC + s1] = mk ? -10000.0f : (p1 + bb2);
                }
            }
        }
    }
    __syncthreads();

    // ---- softmax over S ----
    if (tid < 32) {
        float m = -3.4e38f;
        for (int i = tid; i < Ss; i += 32) m = fmaxf(m, sm[OFF_SC + i]);
        #pragma unroll
        for (int off = 16; off; off >>= 1)
            m = fmaxf(m, __shfl_xor_sync(0xffffffffu, m, off));
        if (tid == 0) sm[OFF_MISC + 0] = m;
    }
    __syncthreads();
    const float smax = sm[OFF_MISC + 0];
    if (tid < Ss) sm[OFF_SC + tid] = __expf(sm[OFF_SC + tid] - smax);
    __syncthreads();
    if (tid < 32) {
        float sum = 0.f;
        for (int i = tid; i < Ss; i += 32) sum += sm[OFF_SC + i];
        #pragma unroll
        for (int off = 16; off; off >>= 1)
            sum += __shfl_xor_sync(0xffffffffu, sum, off);
        if (tid == 0) sm[OFF_MISC + 1] = sum;
    }
    __syncthreads();
    const float inv = 1.0f / sm[OFF_MISC + 1];

    // ---- weighted sum: out[h] = inv * sum_s e[s]*k[s][h] ----
    {
        int h = tid & 63, g = tid >> 6;   // 8 s-groups x 64 h
        float acc = 0.f;
        for (int s = g; s < Ss; s += 8)
            acc += sm[OFF_SC + s] * sm[OFF_K + s * KSTRIDE + h];
        sm[OFF_RED + g * 64 + h] = acc;
    }
    __syncthreads();
    if (tid < Hh) {
        float v = 0.f;
        #pragma unroll
        for (int g = 0; g < 8; g++) v += sm[OFF_RED + g * 64 + tid];
        out[(size_t)bw * Hh + tid] = v * inv;
    }
}

extern "C" void kernel_launch(void* const* d_in, const int* in_sizes, int n_in,
                              void* d_out, int out_size) {
    const float* query          = (const float*)d_in[0];
    const float* key            = (const float*)d_in[1];
    const float* W1             = (const float*)d_in[2];
    const float* b1             = (const float*)d_in[3];
    const float* prelu_a        = (const float*)d_in[4];
    const float* W2             = (const float*)d_in[5];
    const float* b2             = (const float*)d_in[6];
    const void*  mask           = (const void*)d_in[7];
    float* out = (float*)d_out;

    const int B = in_sizes[0] / Hh;      // 512
    const int grid = B * Ww;             // 4096 CTAs, one per (b,w)
    const int smem_bytes = SMEM_FLOATS * sizeof(float);   // ~81.8 KB

    detect_mask_layout<<<1, 256>>>((const unsigned int*)mask, 1024);

    cudaFuncSetAttribute(twb_kernel,
                         cudaFuncAttributeMaxDynamicSharedMemorySize, smem_bytes);
    twb_kernel<<<grid, NTHREADS, smem_bytes>>>(
        query, key, W1, b1, prelu_a, W2, b2, mask, out);
}